// round 1
// baseline (speedup 1.0000x reference)
#include <cuda_runtime.h>
#include <cstdint>

#define PLANE 65536   // 256*256

// DCNv2: B=2, C=64, O=64, H=W=256, 3x3, pad=1.
// Thread = one output pixel, 64 output channels accumulated as 32 f32x2 pairs.
// Weight staged transposed into SMEM in two 32-channel passes (76KB -> 2 CTAs/SM).
__global__ __launch_bounds__(256, 2)
void dcn_kernel(const float* __restrict__ x,
                const float* __restrict__ wgt,
                const float* __restrict__ off,
                const float* __restrict__ msk,
                float* __restrict__ out)
{
    extern __shared__ float sF[];   // 288 * 66 floats = 76032 B (padded rows: stride 66)
    const int r = blockIdx.x;       // 0..511: b*256 + h
    const int b = r >> 8;
    const int h = r & 255;
    const int w = threadIdx.x;      // 0..255
    const int p = (h << 8) | w;

    unsigned long long acc[32];
#pragma unroll
    for (int j = 0; j < 32; ++j) acc[j] = 0ULL;

    const float* offb = off + (size_t)b * 18 * PLANE + p;
    const float* mskb = msk + (size_t)b * 9  * PLANE + p;
    const float* xb   = x   + (size_t)b * 64 * PLANE;

    for (int cpass = 0; cpass < 2; ++cpass) {
        const int c0 = cpass << 5;          // 0 or 32

        // Stage weight slice w[o][c0..c0+31][k] transposed -> sF[(cl*9+k)*66 + o]
        __syncthreads();                    // protect previous pass's readers
        for (int i = threadIdx.x; i < 18432; i += 256) {
            const int o = i / 288;          // 0..63
            const int j = i - o * 288;      // ck-local 0..287 (coalesced gmem read)
            sF[j * 66 + o] = wgt[o * 576 + c0 * 9 + j];
        }
        __syncthreads();

        for (int k = 0; k < 9; ++k) {
            const float oy = __ldg(offb + (2 * k)     * PLANE);
            const float ox = __ldg(offb + (2 * k + 1) * PLANE);
            const float m  = __ldg(mskb + k * PLANE);
            const int ky = k / 3;
            const int kx = k - ky * 3;

            const float py = oy + (float)(h - 1 + ky);
            const float px = ox + (float)(w - 1 + kx);
            const float y0f = floorf(py);
            const float x0f = floorf(px);
            const float dy = py - y0f;
            const float dx = px - x0f;
            const int y0 = (int)y0f;
            const int x0 = (int)x0f;
            const int y1 = y0 + 1;
            const int x1 = x0 + 1;
            const bool vy0 = (unsigned)y0 < 256u;
            const bool vy1 = (unsigned)y1 < 256u;
            const bool vx0 = (unsigned)x0 < 256u;
            const bool vx1 = (unsigned)x1 < 256u;
            const int cy0 = min(max(y0, 0), 255);
            const int cy1 = min(max(y1, 0), 255);
            const int cx0 = min(max(x0, 0), 255);
            const int cx1 = min(max(x1, 0), 255);
            // mask + validity folded into per-corner coefficients
            const float a00 = (vy0 && vx0) ? (1.f - dy) * (1.f - dx) * m : 0.f;
            const float a01 = (vy0 && vx1) ? (1.f - dy) * dx        * m : 0.f;
            const float a10 = (vy1 && vx0) ? dy        * (1.f - dx) * m : 0.f;
            const float a11 = (vy1 && vx1) ? dy        * dx        * m : 0.f;
            const int i00 = (cy0 << 8) | cx0;
            const int i01 = (cy0 << 8) | cx1;
            const int i10 = (cy1 << 8) | cx0;
            const int i11 = (cy1 << 8) | cx1;

            // depth-2 software pipeline over channels
            const float* xc = xb + (size_t)c0 * PLANE;
            float qa[2], qb[2], qc[2], qd[2];
            qa[0] = __ldg(xc + i00);          qb[0] = __ldg(xc + i01);
            qc[0] = __ldg(xc + i10);          qd[0] = __ldg(xc + i11);
            qa[1] = __ldg(xc + PLANE + i00);  qb[1] = __ldg(xc + PLANE + i01);
            qc[1] = __ldg(xc + PLANE + i10);  qd[1] = __ldg(xc + PLANE + i11);
            const float* xpre = xc + 2 * PLANE;

#pragma unroll 2
            for (int c = 0; c < 32; ++c) {
                const int s = c & 1;
                const float v00 = qa[s], v01 = qb[s], v10 = qc[s], v11 = qd[s];
                if (c < 30) {
                    qa[s] = __ldg(xpre + i00);
                    qb[s] = __ldg(xpre + i01);
                    qc[s] = __ldg(xpre + i10);
                    qd[s] = __ldg(xpre + i11);
                    xpre += PLANE;
                }
                const float val = a00 * v00 + a01 * v01 + a10 * v10 + a11 * v11;
                unsigned long long v2;
                asm("mov.b64 %0, {%1, %1};" : "=l"(v2) : "f"(val));
                const unsigned long long* wrow =
                    reinterpret_cast<const unsigned long long*>(sF + (c * 9 + k) * 66);
#pragma unroll
                for (int j = 0; j < 32; ++j) {
                    // packed fp32 FMA: two output channels per instruction
                    asm("fma.rn.f32x2 %0, %1, %2, %0;"
                        : "+l"(acc[j]) : "l"(v2), "l"(wrow[j]));
                }
            }
        }
    }

    float* outp = out + (size_t)b * 64 * PLANE + p;
#pragma unroll
    for (int j = 0; j < 32; ++j) {
        float lo, hi;
        asm("mov.b64 {%0, %1}, %2;" : "=f"(lo), "=f"(hi) : "l"(acc[j]));
        outp[(2 * j)     * PLANE] = lo;
        outp[(2 * j + 1) * PLANE] = hi;
    }
}

extern "C" void kernel_launch(void* const* d_in, const int* in_sizes, int n_in,
                              void* d_out, int out_size)
{
    const float* x   = (const float*)d_in[0];
    const float* wgt = (const float*)d_in[1];
    const float* off = (const float*)d_in[2];
    const float* msk = (const float*)d_in[3];
    float* out = (float*)d_out;

    cudaFuncSetAttribute(dcn_kernel, cudaFuncAttributeMaxDynamicSharedMemorySize, 76032);
    dcn_kernel<<<512, 256, 76032>>>(x, wgt, off, msk, out);
}

// round 2
// speedup vs baseline: 1.0621x; 1.0621x over previous
#include <cuda_runtime.h>
#include <cstdint>

#define PLANE 65536   // 256*256

// Pre-transposed weights: wT[k][c][o]
__device__ float g_wT[9][64][64];

__global__ void wt_transpose(const float* __restrict__ wgt)
{
    int i = blockIdx.x * 256 + threadIdx.x;   // 64*64*9 = 36864 elems, coalesced read
    if (i < 36864) {
        int o = i / 576;
        int r = i - o * 576;
        int c = r / 9;
        int k = r - c * 9;
        g_wT[k][c][o] = wgt[i];
    }
}

// CTA = 128 contiguous pixels (half an image row) x all 64 output channels.
// Per kernel tap k: gather val[64c][128p] into SMEM, stage w_k as {w,w} u64,
// then register-tiled GEMM: thread = 8 o x 4 p via 16 packed f32x2 FMAs/step.
__global__ __launch_bounds__(256, 2)
void dcn_main(const float* __restrict__ x,
              const float* __restrict__ off,
              const float* __restrict__ msk,
              float* __restrict__ out)
{
    extern __shared__ float smem[];
    unsigned long long* wdup = (unsigned long long*)smem;  // [64c][64o] u64 {w,w}: 32768 B
    float* val  = smem + 8192;                             // [64c][128p] f32: 32768 B
    float* outs = smem + 8192;                             // reuse: [64o][132] f32: 33792 B

    const int t   = threadIdx.x;
    const int gp0 = blockIdx.x * 128;     // global pixel (over both batches)
    const int b   = gp0 >> 16;
    const int p0  = gp0 & 65535;          // pixel within batch
    const int h   = p0 >> 8;
    const int w0  = p0 & 255;

    // GEMM-role indices
    const int og = t & 7;                 // o-group (8 groups)
    const int pg = t >> 3;                // pixel-group (32 groups of 4)

    // gather-role indices
    const int gpix = t & 127;             // pixel within tile
    const int c0g  = (t >> 7) << 5;       // channel half: 0 or 32
    const int gw   = w0 + gpix;

    const float* offp = off + (size_t)b * 18 * PLANE + p0 + gpix;
    const float* mskp = msk + (size_t)b * 9  * PLANE + p0 + gpix;
    const float* xb   = x + ((size_t)b * 64 + c0g) * PLANE;

    unsigned long long acc[8][2];
#pragma unroll
    for (int j = 0; j < 8; ++j) { acc[j][0] = 0ULL; acc[j][1] = 0ULL; }

    for (int k = 0; k < 9; ++k) {
        __syncthreads();   // protect wdup/val from previous GEMM's readers

        // ---- stage weights, duplicated into u64 lanes ----
        const float* wk = &g_wT[k][0][0];   // 4096 floats, contiguous
#pragma unroll
        for (int j = 0; j < 16; ++j) {
            const int idx = (j << 8) + t;   // = c*64 + o
            const float wv = wk[idx];
            unsigned long long d;
            asm("mov.b64 %0, {%1, %1};" : "=l"(d) : "f"(wv));
            wdup[idx] = d;
        }

        // ---- bilinear gather of val[c][p] for this tap ----
        const float oy = __ldg(offp + (2 * k)     * PLANE);
        const float ox = __ldg(offp + (2 * k + 1) * PLANE);
        const float m  = __ldg(mskp + k * PLANE);
        const int ky = k / 3;
        const int kx = k - ky * 3;

        const float py  = oy + (float)(h  - 1 + ky);
        const float px  = ox + (float)(gw - 1 + kx);
        const float y0f = floorf(py);
        const float x0f = floorf(px);
        const float dy = py - y0f;
        const float dx = px - x0f;
        const int y0 = (int)y0f, x0 = (int)x0f;
        const int y1 = y0 + 1,   x1 = x0 + 1;
        const bool vy0 = (unsigned)y0 < 256u;
        const bool vy1 = (unsigned)y1 < 256u;
        const bool vx0 = (unsigned)x0 < 256u;
        const bool vx1 = (unsigned)x1 < 256u;
        const int cy0 = min(max(y0, 0), 255);
        const int cy1 = min(max(y1, 0), 255);
        const int cx0 = min(max(x0, 0), 255);
        const int cx1 = min(max(x1, 0), 255);
        const float a00 = (vy0 && vx0) ? (1.f - dy) * (1.f - dx) * m : 0.f;
        const float a01 = (vy0 && vx1) ? (1.f - dy) * dx         * m : 0.f;
        const float a10 = (vy1 && vx0) ? dy         * (1.f - dx) * m : 0.f;
        const float a11 = (vy1 && vx1) ? dy         * dx         * m : 0.f;
        const int i00 = (cy0 << 8) | cx0;
        const int i01 = (cy0 << 8) | cx1;
        const int i10 = (cy1 << 8) | cx0;
        const int i11 = (cy1 << 8) | cx1;

        float* vcol = val + gpix;
#pragma unroll 4
        for (int c = 0; c < 32; ++c) {
            const float* xp = xb + (size_t)c * PLANE;
            const float v00 = __ldg(xp + i00);
            const float v01 = __ldg(xp + i01);
            const float v10 = __ldg(xp + i10);
            const float v11 = __ldg(xp + i11);
            vcol[(c0g + c) << 7] = a00 * v00 + a01 * v01 + a10 * v10 + a11 * v11;
        }

        __syncthreads();

        // ---- register-tiled GEMM over this tap's 64 channels ----
        const unsigned long long* wr = wdup + (og << 1);
        const unsigned long long* vr = (const unsigned long long*)val + (pg << 1);
#pragma unroll 2
        for (int c = 0; c < 64; ++c) {
            const ulonglong2 wq0 = *(const ulonglong2*)(wr + c * 64);
            const ulonglong2 wq1 = *(const ulonglong2*)(wr + c * 64 + 16);
            const ulonglong2 wq2 = *(const ulonglong2*)(wr + c * 64 + 32);
            const ulonglong2 wq3 = *(const ulonglong2*)(wr + c * 64 + 48);
            const ulonglong2 vv  = *(const ulonglong2*)(vr + c * 64);

            asm("fma.rn.f32x2 %0, %1, %2, %0;" : "+l"(acc[0][0]) : "l"(wq0.x), "l"(vv.x));
            asm("fma.rn.f32x2 %0, %1, %2, %0;" : "+l"(acc[0][1]) : "l"(wq0.x), "l"(vv.y));
            asm("fma.rn.f32x2 %0, %1, %2, %0;" : "+l"(acc[1][0]) : "l"(wq0.y), "l"(vv.x));
            asm("fma.rn.f32x2 %0, %1, %2, %0;" : "+l"(acc[1][1]) : "l"(wq0.y), "l"(vv.y));
            asm("fma.rn.f32x2 %0, %1, %2, %0;" : "+l"(acc[2][0]) : "l"(wq1.x), "l"(vv.x));
            asm("fma.rn.f32x2 %0, %1, %2, %0;" : "+l"(acc[2][1]) : "l"(wq1.x), "l"(vv.y));
            asm("fma.rn.f32x2 %0, %1, %2, %0;" : "+l"(acc[3][0]) : "l"(wq1.y), "l"(vv.x));
            asm("fma.rn.f32x2 %0, %1, %2, %0;" : "+l"(acc[3][1]) : "l"(wq1.y), "l"(vv.y));
            asm("fma.rn.f32x2 %0, %1, %2, %0;" : "+l"(acc[4][0]) : "l"(wq2.x), "l"(vv.x));
            asm("fma.rn.f32x2 %0, %1, %2, %0;" : "+l"(acc[4][1]) : "l"(wq2.x), "l"(vv.y));
            asm("fma.rn.f32x2 %0, %1, %2, %0;" : "+l"(acc[5][0]) : "l"(wq2.y), "l"(vv.x));
            asm("fma.rn.f32x2 %0, %1, %2, %0;" : "+l"(acc[5][1]) : "l"(wq2.y), "l"(vv.y));
            asm("fma.rn.f32x2 %0, %1, %2, %0;" : "+l"(acc[6][0]) : "l"(wq3.x), "l"(vv.x));
            asm("fma.rn.f32x2 %0, %1, %2, %0;" : "+l"(acc[6][1]) : "l"(wq3.x), "l"(vv.y));
            asm("fma.rn.f32x2 %0, %1, %2, %0;" : "+l"(acc[7][0]) : "l"(wq3.y), "l"(vv.x));
            asm("fma.rn.f32x2 %0, %1, %2, %0;" : "+l"(acc[7][1]) : "l"(wq3.y), "l"(vv.y));
        }
    }

    // ---- epilogue: transpose via SMEM for coalesced global stores ----
    __syncthreads();   // last GEMM readers done before outs overwrites val
#pragma unroll
    for (int q = 0; q < 4; ++q) {
#pragma unroll
        for (int s = 0; s < 2; ++s) {
            const int o = (og << 1) + (q << 4) + s;
            const int j = (q << 1) + s;
            *(unsigned long long*)(outs + o * 132 + (pg << 2))     = acc[j][0];
            *(unsigned long long*)(outs + o * 132 + (pg << 2) + 2) = acc[j][1];
        }
    }
    __syncthreads();

    float* ob = out + (size_t)b * 64 * PLANE + p0;
    const int lane = t & 31;
    const int g32  = t >> 5;
#pragma unroll
    for (int i = 0; i < 8; ++i) {
        const int o = (i << 3) + g32;
        const float4 v = *(const float4*)(outs + o * 132 + (lane << 2));
        *(float4*)(ob + (size_t)o * PLANE + (lane << 2)) = v;
    }
}

extern "C" void kernel_launch(void* const* d_in, const int* in_sizes, int n_in,
                              void* d_out, int out_size)
{
    const float* x   = (const float*)d_in[0];
    const float* wgt = (const float*)d_in[1];
    const float* off = (const float*)d_in[2];
    const float* msk = (const float*)d_in[3];
    float* out = (float*)d_out;

    wt_transpose<<<144, 256>>>(wgt);

    cudaFuncSetAttribute(dcn_main, cudaFuncAttributeMaxDynamicSharedMemorySize, 66560);
    dcn_main<<<1024, 256, 66560>>>(x, off, msk, out);
}